// round 2
// baseline (speedup 1.0000x reference)
#include <cuda_runtime.h>
#include <math.h>
#include <stdint.h>

// Problem dims (fixed by the reference)
#define BATCH 16384
#define D_IN  1024
#define H_DIM 2048
#define O_DIM 2

#define DW (D_IN / 32)   // 32 words per row of packed x / w1
#define HW (H_DIM / 32)  // 64 words per row of packed hidden act / w2,w3,wout

// -------- scratch (device globals; no allocation allowed) --------
__device__ unsigned g_actA[BATCH * HW];          // 4 MB  (also holds packed x: BATCH x DW)
__device__ unsigned g_actB[BATCH * HW];          // 4 MB
__device__ unsigned g_w1b [H_DIM * DW];
__device__ unsigned g_w2b [H_DIM * HW];
__device__ unsigned g_w3b [H_DIM * HW];
__device__ unsigned g_woutb[O_DIM * HW];
__device__ float    g_thr [3 * H_DIM];

// -------- BN thresholds: sign((C-m)*g/sqrt(v+eps)+b) < 0  <=>  C < m - b*sqrt(v+eps)/g
__global__ void compute_thr_kernel(const float* __restrict__ g, const float* __restrict__ b,
                                   const float* __restrict__ m, const float* __restrict__ v,
                                   float* __restrict__ thr)
{
    int i = blockIdx.x * blockDim.x + threadIdx.x;
    if (i < H_DIM)
        thr[i] = m[i] - b[i] * sqrtf(v[i] + 1e-5f) / g[i];
}

// -------- pack sign bits: bit = (src < cmp). One warp -> one 32-bit word.
__global__ void pack_bits_kernel(const float* __restrict__ src, unsigned* __restrict__ dst,
                                 int nwords, float cmp)
{
    int gid  = blockIdx.x * blockDim.x + threadIdx.x;
    int w    = gid >> 5;
    if (w >= nwords) return;               // whole warp exits together
    int lane = gid & 31;
    float v  = src[(size_t)w * 32 + lane];
    unsigned msk = __ballot_sync(0xffffffffu, v < cmp);
    if (lane == 0) dst[w] = msk;
}

// -------- binary GEMM + BN + sign, packed output.
// Tile: 64 rows x 128 cols, 256 threads (8 warps).
// Warp w -> rows [w*8, w*8+8). Lane l -> cols c0 + j*32 + l, j=0..3.
// dot = Kbits - 2*popc_sum; out bit = ((float)dot < thr[col]); repacked via ballot.
template <int KW>
__global__ __launch_bounds__(256)
void bgemm_bn_sign(const unsigned* __restrict__ A,   // [M][KW]
                   const unsigned* __restrict__ W,   // [N][KW]
                   const float*    __restrict__ thr, // [N]
                   unsigned*       __restrict__ Out, // [M][N/32] (N/32 == HW here)
                   int Kbits)
{
    __shared__ unsigned sA[64  * KW];   // row-major, broadcast reads
    __shared__ unsigned sW[128 * KW];   // XOR-swizzled: element (row,k) at row*KW + (k ^ (row&31))

    const int tid  = threadIdx.x;
    const int lane = tid & 31;
    const int warp = tid >> 5;
    const int r0   = blockIdx.x * 64;
    const int c0   = blockIdx.y * 128;

    #pragma unroll
    for (int idx = tid; idx < 64 * KW; idx += 256)
        sA[idx] = A[(size_t)(r0 + idx / KW) * KW + (idx % KW)];

    #pragma unroll
    for (int idx = tid; idx < 128 * KW; idx += 256) {
        int row = idx / KW, k = idx % KW;
        sW[row * KW + (k ^ (row & 31))] = W[(size_t)(c0 + row) * KW + k];
    }
    __syncthreads();

    int acc[8][4];
    #pragma unroll
    for (int r = 0; r < 8; ++r)
        #pragma unroll
        for (int j = 0; j < 4; ++j) acc[r][j] = 0;

    const unsigned* aBase = sA + warp * 8 * KW;

    #pragma unroll 8
    for (int k = 0; k < KW; ++k) {
        unsigned av[8];
        #pragma unroll
        for (int r = 0; r < 8; ++r) av[r] = aBase[r * KW + k];     // broadcast LDS
        const int ks = k ^ lane;                                    // matches store swizzle (col&31 == lane)
        unsigned wv[4];
        #pragma unroll
        for (int j = 0; j < 4; ++j) wv[j] = sW[(j * 32 + lane) * KW + ks];
        #pragma unroll
        for (int r = 0; r < 8; ++r)
            #pragma unroll
            for (int j = 0; j < 4; ++j)
                acc[r][j] += __popc(av[r] ^ wv[j]);
    }

    // epilogue: BN-threshold compare + warp-ballot repack
    float t[4];
    #pragma unroll
    for (int j = 0; j < 4; ++j) t[j] = thr[c0 + j * 32 + lane];

    const int outw0 = c0 >> 5;
    #pragma unroll
    for (int r = 0; r < 8; ++r) {
        int row = r0 + warp * 8 + r;
        #pragma unroll
        for (int j = 0; j < 4; ++j) {
            float C = (float)(Kbits - 2 * acc[r][j]);
            unsigned msk = __ballot_sync(0xffffffffu, C < t[j]);
            if (lane == j) Out[(size_t)row * HW + outw0 + j] = msk;
        }
    }
}

// -------- final layer: out[B][2] = h3b @ binq(wout)^T (float32)
__global__ __launch_bounds__(256)
void final_layer_kernel(const unsigned* __restrict__ A,   // [B][HW]
                        const unsigned* __restrict__ Wb,  // [2][HW]
                        float* __restrict__ out)          // [B][2]
{
    __shared__ unsigned sw[2 * HW];
    if (threadIdx.x < 2 * HW) sw[threadIdx.x] = Wb[threadIdx.x];
    __syncthreads();

    int row = blockIdx.x * blockDim.x + threadIdx.x;
    const unsigned* ar = A + (size_t)row * HW;
    int a0 = 0, a1 = 0;
    #pragma unroll
    for (int k = 0; k < HW; ++k) {
        unsigned a = ar[k];
        a0 += __popc(a ^ sw[k]);
        a1 += __popc(a ^ sw[HW + k]);
    }
    out[row * 2 + 0] = (float)(H_DIM - 2 * a0);
    out[row * 2 + 1] = (float)(H_DIM - 2 * a1);
}

// ----------------------------------------------------------------------------
extern "C" void kernel_launch(void* const* d_in, const int* in_sizes, int n_in,
                              void* d_out, int out_size)
{
    const float* x    = (const float*)d_in[0];
    const float* w1   = (const float*)d_in[1];
    const float* g1   = (const float*)d_in[2];
    const float* b1   = (const float*)d_in[3];
    const float* m1   = (const float*)d_in[4];
    const float* v1   = (const float*)d_in[5];
    const float* w2   = (const float*)d_in[6];
    const float* g2   = (const float*)d_in[7];
    const float* b2   = (const float*)d_in[8];
    const float* m2   = (const float*)d_in[9];
    const float* v2   = (const float*)d_in[10];
    const float* w3   = (const float*)d_in[11];
    const float* g3   = (const float*)d_in[12];
    const float* b3   = (const float*)d_in[13];
    const float* m3   = (const float*)d_in[14];
    const float* v3   = (const float*)d_in[15];
    const float* wout = (const float*)d_in[16];
    float* out = (float*)d_out;

    unsigned *actA, *actB, *w1b, *w2b, *w3b, *woutb;
    float* thr;
    cudaGetSymbolAddress((void**)&actA,  g_actA);
    cudaGetSymbolAddress((void**)&actB,  g_actB);
    cudaGetSymbolAddress((void**)&w1b,   g_w1b);
    cudaGetSymbolAddress((void**)&w2b,   g_w2b);
    cudaGetSymbolAddress((void**)&w3b,   g_w3b);
    cudaGetSymbolAddress((void**)&woutb, g_woutb);
    cudaGetSymbolAddress((void**)&thr,   g_thr);

    // BN thresholds (3 layers)
    compute_thr_kernel<<<(H_DIM + 255) / 256, 256>>>(g1, b1, m1, v1, thr);
    compute_thr_kernel<<<(H_DIM + 255) / 256, 256>>>(g2, b2, m2, v2, thr + H_DIM);
    compute_thr_kernel<<<(H_DIM + 255) / 256, 256>>>(g3, b3, m3, v3, thr + 2 * H_DIM);

    // pack x: binq(2x-1) -> bit = (x < 0.5)
    {
        int nw = BATCH * DW;
        pack_bits_kernel<<<(nw * 32 + 255) / 256, 256>>>(x, actA, nw, 0.5f);
    }
    // pack weights: bit = (w < 0)
    {
        int nw = H_DIM * DW;
        pack_bits_kernel<<<(nw * 32 + 255) / 256, 256>>>(w1, w1b, nw, 0.0f);
        nw = H_DIM * HW;
        pack_bits_kernel<<<(nw * 32 + 255) / 256, 256>>>(w2, w2b, nw, 0.0f);
        pack_bits_kernel<<<(nw * 32 + 255) / 256, 256>>>(w3, w3b, nw, 0.0f);
        nw = O_DIM * HW;
        pack_bits_kernel<<<(nw * 32 + 255) / 256, 256>>>(wout, woutb, nw, 0.0f);
    }

    dim3 block(256);
    dim3 grid1(BATCH / 64, H_DIM / 128);

    // layer 1: actA(packed x, KW=32) -> actB
    bgemm_bn_sign<DW><<<grid1, block>>>(actA, w1b, thr,             actB, D_IN);
    // layer 2: actB -> actA
    bgemm_bn_sign<HW><<<grid1, block>>>(actB, w2b, thr + H_DIM,     actA, H_DIM);
    // layer 3: actA -> actB
    bgemm_bn_sign<HW><<<grid1, block>>>(actA, w3b, thr + 2 * H_DIM, actB, H_DIM);

    // final: actB -> out (float)
    final_layer_kernel<<<BATCH / 256, 256>>>(actB, woutb, out);
}